// round 10
// baseline (speedup 1.0000x reference)
#include <cuda_runtime.h>
#include <math.h>

// Problem constants
#define NIMG   4
#define HW     48
#define CH     3
#define NPIX   6912              // per image
#define KS     21
#define KR     10

// Config
#define TPTS   65                // x-grid: t/64, t=0..64
#define GRID   144               // 1 block/SM -> all co-resident, safe spin barrier
#define TB     512
#define YT     4                 // output rows per conv tile (144 = 4n*3c*12)
#define TROWS  (YT + KS - 1)     // 24
#define TCOLS  (HW + KS - 1)     // 68
#define BPI    36                // blocks per image

// Scratch (device globals; no allocation). d_part overwritten each run.
__device__ float d_part[NIMG][BPI][TPTS];
__device__ unsigned g_cntb[NIMG];
__device__ unsigned g_genb[NIMG];

// Shared pool (floats):
//  persist: IN @0 (1632), KG@1632 KM@1656 KW@1680, M @1704 (192), F @1896 (192)
//  P1: H1 @2088 (1152), H2 @3240 (1152), VP1 @4392 (384), VP2 @4776 (384)
//  P2: PRT @2088 (390, reuses H1)
//  P3: TBL @2088 (66), DF @2160 (1632), H3 @3852 (1152), VP3 @5008 (384)
//      (VP3 is DISJOINT from H3: 5008 >= 3852+1152 — R9's race fixed)
#define SP_IN   0
#define SP_KG   1632
#define SP_KM   1656
#define SP_KW   1680
#define SP_M    1704
#define SP_F    1896
#define SP_H1   2088
#define SP_H2   3240
#define SP_VP1  4392
#define SP_VP2  4776
#define SP_PRT  2088
#define SP_TBL  2088
#define SP_DF   2160
#define SP_H3   3852
#define SP_VP3  5008
#define POOL    5392             // 21568 B static smem

__device__ __forceinline__ float frcp(float x) {
    float r; asm("rcp.approx.f32 %0, %1;" : "=f"(r) : "f"(x)); return r;
}

// f32x2 packed helpers (FFMA2 via PTX fma.rn.f32x2)
__device__ __forceinline__ unsigned long long pack2(float lo, float hi) {
    unsigned long long d;
    asm("mov.b64 %0, {%1, %2};" : "=l"(d) : "r"(__float_as_uint(lo)), "r"(__float_as_uint(hi)));
    return d;
}
__device__ __forceinline__ void unpack2(unsigned long long v, float& lo, float& hi) {
    unsigned a, b;
    asm("mov.b64 {%0, %1}, %2;" : "=r"(a), "=r"(b) : "l"(v));
    lo = __uint_as_float(a); hi = __uint_as_float(b);
}
__device__ __forceinline__ void fma2(unsigned long long& acc,
                                     unsigned long long a, unsigned long long b) {
    asm("fma.rn.f32x2 %0, %1, %2, %0;" : "+l"(acc) : "l"(a), "l"(b));
}

// Per-image spin barrier (monotone generation; 36 co-resident blocks/image).
__device__ __forceinline__ void imgbar(int idx) {
    __syncthreads();
    __threadfence();
    if (threadIdx.x == 0) {
        volatile unsigned* vgen = (volatile unsigned*)&g_genb[idx];
        unsigned gen = *vgen;
        if (atomicAdd(&g_cntb[idx], 1u) == BPI - 1) {
            g_cntb[idx] = 0;
            __threadfence();
            *vgen = gen + 1;
        } else {
            while (*vgen == gen) {}
        }
    }
    __syncthreads();
    __threadfence();
}

// One warp builds a unit-L2 1D Gaussian (2D kernel = exact outer product).
__device__ __forceinline__ void make_k1d(float gamma, float* out) {
    int lane = threadIdx.x & 31;
    float inv2s2 = 0.5f * gamma * gamma;
    const float step = (21.0f / 32.0f) / 20.0f;
    const float mean = 21.0f / 64.0f;
    float v = 0.0f;
    if (lane < KS) {
        float d = (float)lane * step - mean;
        v = expf(-d * d * inv2s2);
    }
    float ss = v * v;
    #pragma unroll
    for (int o = 16; o > 0; o >>= 1) ss += __shfl_xor_sync(0xffffffffu, ss, o);
    if (lane < KS) out[lane] = v * rsqrtf(ss);
}

__global__ __launch_bounds__(TB, 1)
void inrf_fused(const float* __restrict__ in,
                const float* __restrict__ gm,
                const float* __restrict__ gw,
                const float* __restrict__ gg,
                float* __restrict__ out) {
    __shared__ float sp[POOL];

    const int tid  = threadIdx.x;
    const int warp = tid >> 5;

    // Decomposition: 144 = 4n * 36; within image: 3c * 12 ytiles
    const int b   = blockIdx.x;
    const int n   = b / BPI;
    const int rem = b % BPI;
    const int c   = rem / 12;
    const int y0  = (rem % 12) * YT;

    // ---------------- Phase 1: convs + per-block partial tanh-table --------
    if      (warp == 0) make_k1d(gg[c], sp + SP_KG);
    else if (warp == 1) make_k1d(gm[c], sp + SP_KM);
    else if (warp == 2) make_k1d(gw[c], sp + SP_KW);

    // zero-padded input tile (rows y0-10..y0+13, cols -10..57), channel c
    for (int i = tid; i < TROWS * TCOLS; i += TB) {
        int r  = i / TCOLS;
        int xc = i % TCOLS - KR;
        int yy = y0 - KR + r;
        float v = 0.0f;
        if ((unsigned)yy < HW && (unsigned)xc < HW)
            v = in[((n * HW + yy) * HW + xc) * CH + c];
        sp[SP_IN + i] = v;
    }
    __syncthreads();

    // packed taps (lo=G, hi=M) -> registers
    unsigned long long tk[KS];
    #pragma unroll
    for (int k = 0; k < KS; k++) tk[k] = pack2(sp[SP_KG + k], sp[SP_KM + k]);

    // horizontal pass, both convs (packed FMA, 3 independent chains)
    for (int i = tid; i < TROWS * HW; i += TB) {
        int r = i / HW, x = i % HW;
        const float* row = sp + SP_IN + r * TCOLS + x;
        unsigned long long a0 = 0ull, a1 = 0ull, a2 = 0ull;
        #pragma unroll
        for (int k = 0; k < 7; k++) {
            float v0 = row[k], v1 = row[k + 7], v2 = row[k + 14];
            fma2(a0, pack2(v0, v0), tk[k]);
            fma2(a1, pack2(v1, v1), tk[k + 7]);
            fma2(a2, pack2(v2, v2), tk[k + 14]);
        }
        float s1a, s2a, s1b, s2b, s1c, s2c;
        unpack2(a0, s1a, s2a); unpack2(a1, s1b, s2b); unpack2(a2, s1c, s2c);
        sp[SP_H1 + i] = (s1a + s1b) + s1c;     // G partial
        sp[SP_H2 + i] = (s2a + s2b) + s2c;     // M partial
    }
    __syncthreads();

    // vertical pass, split across 384 threads (half taps each, 2 sub-chains)
    if (tid < 384) {
        int o     = (tid >= 192) ? tid - 192 : tid;
        int kbase = (tid >= 192) ? 11 : 0;
        int kn    = (tid >= 192) ? 10 : 11;
        int yo = o / HW, x = o % HW;
        int base = (yo + kbase) * HW + x;
        unsigned long long a0 = 0ull, a1 = 0ull;
        #pragma unroll 2
        for (int k = 0; k + 1 < kn; k += 2) {
            int o0 = base + k * HW, o1 = o0 + HW;
            fma2(a0, pack2(sp[SP_H1 + o0], sp[SP_H2 + o0]), tk[kbase + k]);
            fma2(a1, pack2(sp[SP_H1 + o1], sp[SP_H2 + o1]), tk[kbase + k + 1]);
        }
        if (kn & 1) {
            int o0 = base + (kn - 1) * HW;
            fma2(a0, pack2(sp[SP_H1 + o0], sp[SP_H2 + o0]), tk[kbase + kn - 1]);
        }
        float g0, m0, g1, m1;
        unpack2(a0, g0, m0); unpack2(a1, g1, m1);
        sp[SP_VP1 + tid] = g0 + g1;
        sp[SP_VP2 + tid] = m0 + m1;
    }
    __syncthreads();
    if (tid < 192) {
        float sg = sp[SP_VP1 + tid] + sp[SP_VP1 + tid + 192];
        float sm = sp[SP_VP2 + tid] + sp[SP_VP2 + tid + 192];
        sp[SP_M + tid] = sm;
        sp[SP_F + tid] = __expf(-2.0f * sg);   // e^{-2 blur}
    }
    __syncthreads();

    // partial table: prt[t*6+part] = sum over 32 of this block's 192 F values
    // of 1/(1 + e^{2 t/64} * F).  390 threads, 4 independent rcp chains.
    if (tid < 6 * TPTS) {
        int t    = tid / 6;
        int part = tid - 6 * t;
        float E = __expf((float)t * (2.0f / 64.0f));
        float a0 = 0.f, a1 = 0.f, a2 = 0.f, a3 = 0.f;
        #pragma unroll
        for (int k = 0; k < 32; k += 4) {
            a0 += frcp(fmaf(E, sp[SP_F + part + 6 * k],      1.0f));
            a1 += frcp(fmaf(E, sp[SP_F + part + 6 * k + 6],  1.0f));
            a2 += frcp(fmaf(E, sp[SP_F + part + 6 * k + 12], 1.0f));
            a3 += frcp(fmaf(E, sp[SP_F + part + 6 * k + 18], 1.0f));
        }
        sp[SP_PRT + tid] = (a0 + a1) + (a2 + a3);
    }
    __syncthreads();

    // write this block's 65-entry partial row (plain store, replay-safe)
    if (tid < TPTS) {
        const float* q = sp + SP_PRT + 6 * tid;
        d_part[n][rem][tid] = ((q[0] + q[1]) + (q[2] + q[3])) + (q[4] + q[5]);
    }

    imgbar(n);                                 // single per-image barrier

    // ---------------- Phase 3: reduce table; out = M - W(diff) -------------
    if (tid < TPTS) {
        const float* p = &d_part[n][0][tid];
        float a0 = 0.f, a1 = 0.f, a2 = 0.f, a3 = 0.f;
        #pragma unroll
        for (int s = 0; s < BPI; s += 4) {
            a0 += p[(s + 0) * TPTS];
            a1 += p[(s + 1) * TPTS];
            a2 += p[(s + 2) * TPTS];
            a3 += p[(s + 3) * TPTS];
        }
        sp[SP_TBL + tid] = 1.0f - ((a0 + a1) + (a2 + a3)) * (2.0f / (float)NPIX);
    }
    float tw[KS];
    #pragma unroll
    for (int k = 0; k < KS; k++) tw[k] = sp[SP_KW + k];
    __syncthreads();

    // diff tile from persisted IN tile (zero outside the image)
    for (int i = tid; i < TROWS * TCOLS; i += TB) {
        int r  = i / TCOLS;
        int xc = i % TCOLS - KR;
        int yy = y0 - KR + r;
        float d = 0.0f;
        if ((unsigned)yy < HW && (unsigned)xc < HW) {
            float u = sp[SP_IN + i] * 64.0f;
            u = fminf(fmaxf(u, 0.0f), 63.999f);
            int   i0 = (int)u;
            float fr = u - (float)i0;
            float t0 = sp[SP_TBL + i0], t1 = sp[SP_TBL + i0 + 1];
            d = fmaf(t1 - t0, fr, t0);
        }
        sp[SP_DF + i] = d;
    }
    __syncthreads();

    // horizontal pass (W conv, 3 independent chains)
    for (int i = tid; i < TROWS * HW; i += TB) {
        int r = i / HW, x = i % HW;
        const float* row = sp + SP_DF + r * TCOLS + x;
        float a0 = 0.f, a1 = 0.f, a2 = 0.f;
        #pragma unroll
        for (int k = 0; k < 7; k++) {
            a0 = fmaf(row[k],      tw[k],      a0);
            a1 = fmaf(row[k + 7],  tw[k + 7],  a1);
            a2 = fmaf(row[k + 14], tw[k + 14], a2);
        }
        sp[SP_H3 + i] = (a0 + a1) + a2;
    }
    __syncthreads();

    // vertical pass, split across 384 threads -> DISJOINT scratch VP3
    if (tid < 384) {
        int o     = (tid >= 192) ? tid - 192 : tid;
        int kbase = (tid >= 192) ? 11 : 0;
        int kn    = (tid >= 192) ? 10 : 11;
        int yo = o / HW, x = o % HW;
        int base = (yo + kbase) * HW + x;
        float a0 = 0.f, a1 = 0.f;
        #pragma unroll 2
        for (int k = 0; k + 1 < kn; k += 2) {
            a0 = fmaf(sp[SP_H3 + base + k * HW],       tw[kbase + k],     a0);
            a1 = fmaf(sp[SP_H3 + base + (k + 1) * HW], tw[kbase + k + 1], a1);
        }
        if (kn & 1)
            a0 = fmaf(sp[SP_H3 + base + (kn - 1) * HW], tw[kbase + kn - 1], a0);
        sp[SP_VP3 + tid] = a0 + a1;
    }
    __syncthreads();

    // final subtraction (L = 1)
    if (tid < 192) {
        int yo = tid / HW, x = tid % HW;
        float sw = sp[SP_VP3 + tid] + sp[SP_VP3 + tid + 192];
        out[((n * HW + y0 + yo) * HW + x) * CH + c] = sp[SP_M + tid] - sw;
    }
}

extern "C" void kernel_launch(void* const* d_in, const int* in_sizes, int n_in,
                              void* d_out, int out_size) {
    const float* in = (const float*)d_in[0];
    const float* gm = (const float*)d_in[1];
    const float* gw = (const float*)d_in[2];
    const float* gg = (const float*)d_in[3];
    float* out = (float*)d_out;

    inrf_fused<<<GRID, TB>>>(in, gm, gw, gg, out);
}

// round 11
// speedup vs baseline: 1.1400x; 1.1400x over previous
#include <cuda_runtime.h>
#include <math.h>

// Problem constants
#define NIMG   4
#define HW     48
#define CH     3
#define NPIX   6912              // per image
#define KS     21
#define KR     10

// Config
#define TPTS   65                // x-grid: t/64, t=0..64
#define GRID   144               // 1 block/SM -> all co-resident, safe spin barrier
#define TB     512
#define YT     4                 // output rows per conv tile (144 = 4n*3c*12)
#define TROWS  (YT + KS - 1)     // 24
#define TCOLS  (HW + KS - 1)     // 68
#define BPI    36                // blocks per image

// Scratch (device globals; no allocation). d_part overwritten each run.
__device__ float d_part[NIMG][BPI][TPTS];
__device__ unsigned g_cntb[NIMG];
__device__ unsigned g_genb[NIMG];

// Shared pool (floats):
//  persist: IN @0 (1632), KG@1632 KM@1656 KW@1680, M @1704 (192), F @1896 (192)
//  P1: H1 @2088 (1152), H2 @3240 (1152)            (ends 4392)
//  P2: PRT @2088 (390, reuses H1)
//  P3: TBL @2088 (66), DF @2160 (1632), H3 @3852 (1152), RD @5008 (260)
#define SP_IN   0
#define SP_KG   1632
#define SP_KM   1656
#define SP_KW   1680
#define SP_M    1704
#define SP_F    1896
#define SP_H1   2088
#define SP_H2   3240
#define SP_PRT  2088
#define SP_TBL  2088
#define SP_DF   2160
#define SP_H3   3852
#define SP_RD   5008
#define POOL    5280             // 21120 B static smem

__device__ __forceinline__ float frcp(float x) {
    float r; asm("rcp.approx.f32 %0, %1;" : "=f"(r) : "f"(x)); return r;
}

// f32x2 packed helpers (FFMA2 via PTX fma.rn.f32x2)
__device__ __forceinline__ unsigned long long pack2(float lo, float hi) {
    unsigned long long d;
    asm("mov.b64 %0, {%1, %2};" : "=l"(d) : "r"(__float_as_uint(lo)), "r"(__float_as_uint(hi)));
    return d;
}
__device__ __forceinline__ void unpack2(unsigned long long v, float& lo, float& hi) {
    unsigned a, b;
    asm("mov.b64 {%0, %1}, %2;" : "=r"(a), "=r"(b) : "l"(v));
    lo = __uint_as_float(a); hi = __uint_as_float(b);
}
__device__ __forceinline__ void fma2(unsigned long long& acc,
                                     unsigned long long a, unsigned long long b) {
    asm("fma.rn.f32x2 %0, %1, %2, %0;" : "+l"(acc) : "l"(a), "l"(b));
}

// Per-image spin barrier (monotone generation; 36 co-resident blocks/image).
__device__ __forceinline__ void imgbar(int idx) {
    __syncthreads();
    __threadfence();
    if (threadIdx.x == 0) {
        volatile unsigned* vgen = (volatile unsigned*)&g_genb[idx];
        unsigned gen = *vgen;
        if (atomicAdd(&g_cntb[idx], 1u) == BPI - 1) {
            g_cntb[idx] = 0;
            __threadfence();
            *vgen = gen + 1;
        } else {
            while (*vgen == gen) {}
        }
    }
    __syncthreads();
    __threadfence();
}

// One warp builds a unit-L2 1D Gaussian (2D kernel = exact outer product).
__device__ __forceinline__ void make_k1d(float gamma, float* out) {
    int lane = threadIdx.x & 31;
    float inv2s2 = 0.5f * gamma * gamma;
    const float step = (21.0f / 32.0f) / 20.0f;
    const float mean = 21.0f / 64.0f;
    float v = 0.0f;
    if (lane < KS) {
        float d = (float)lane * step - mean;
        v = expf(-d * d * inv2s2);
    }
    float ss = v * v;
    #pragma unroll
    for (int o = 16; o > 0; o >>= 1) ss += __shfl_xor_sync(0xffffffffu, ss, o);
    if (lane < KS) out[lane] = v * rsqrtf(ss);
}

__global__ __launch_bounds__(TB, 1)
void inrf_fused(const float* __restrict__ in,
                const float* __restrict__ gm,
                const float* __restrict__ gw,
                const float* __restrict__ gg,
                float* __restrict__ out) {
    __shared__ float sp[POOL];

    const int tid  = threadIdx.x;
    const int warp = tid >> 5;

    // Decomposition: 144 = 4n * 36; within image: 3c * 12 ytiles
    const int b   = blockIdx.x;
    const int n   = b / BPI;
    const int rem = b % BPI;
    const int c   = rem / 12;
    const int y0  = (rem % 12) * YT;

    // ---------------- Phase 1: convs + per-block partial tanh-table --------
    if      (warp == 0) make_k1d(gg[c], sp + SP_KG);
    else if (warp == 1) make_k1d(gm[c], sp + SP_KM);
    else if (warp == 2) make_k1d(gw[c], sp + SP_KW);

    // zero-padded input tile (rows y0-10..y0+13, cols -10..57), channel c
    for (int i = tid; i < TROWS * TCOLS; i += TB) {
        int r  = i / TCOLS;
        int xc = i % TCOLS - KR;
        int yy = y0 - KR + r;
        float v = 0.0f;
        if ((unsigned)yy < HW && (unsigned)xc < HW)
            v = in[((n * HW + yy) * HW + xc) * CH + c];
        sp[SP_IN + i] = v;
    }
    __syncthreads();

    // packed taps (lo=G, hi=M) -> registers
    unsigned long long tk[KS];
    #pragma unroll
    for (int k = 0; k < KS; k++) tk[k] = pack2(sp[SP_KG + k], sp[SP_KM + k]);

    // horizontal pass, both convs (packed FMA, 3 independent chains)
    for (int i = tid; i < TROWS * HW; i += TB) {
        int r = i / HW, x = i % HW;
        const float* row = sp + SP_IN + r * TCOLS + x;
        unsigned long long a0 = 0ull, a1 = 0ull, a2 = 0ull;
        #pragma unroll
        for (int k = 0; k < 7; k++) {
            float v0 = row[k], v1 = row[k + 7], v2 = row[k + 14];
            fma2(a0, pack2(v0, v0), tk[k]);
            fma2(a1, pack2(v1, v1), tk[k + 7]);
            fma2(a2, pack2(v2, v2), tk[k + 14]);
        }
        float s1a, s2a, s1b, s2b, s1c, s2c;
        unpack2(a0, s1a, s2a); unpack2(a1, s1b, s2b); unpack2(a2, s1c, s2c);
        sp[SP_H1 + i] = (s1a + s1b) + s1c;     // G partial
        sp[SP_H2 + i] = (s2a + s2b) + s2c;     // M partial
    }
    __syncthreads();

    // vertical pass (192 threads, full 21 taps, 3 independent chains):
    // M -> smem;  F = exp(-2*blur) -> smem
    if (tid < YT * HW) {
        int yo = tid / HW, x = tid % HW;
        unsigned long long a0 = 0ull, a1 = 0ull, a2 = 0ull;
        #pragma unroll
        for (int k = 0; k < 7; k++) {
            int o0 = (yo + k) * HW + x;
            int o1 = (yo + k + 7) * HW + x;
            int o2 = (yo + k + 14) * HW + x;
            fma2(a0, pack2(sp[SP_H1 + o0], sp[SP_H2 + o0]), tk[k]);
            fma2(a1, pack2(sp[SP_H1 + o1], sp[SP_H2 + o1]), tk[k + 7]);
            fma2(a2, pack2(sp[SP_H1 + o2], sp[SP_H2 + o2]), tk[k + 14]);
        }
        float g0, m0, g1, m1, g2, m2;
        unpack2(a0, g0, m0); unpack2(a1, g1, m1); unpack2(a2, g2, m2);
        sp[SP_M + tid] = (m0 + m1) + m2;
        sp[SP_F + tid] = __expf(-2.0f * ((g0 + g1) + g2));   // e^{-2 blur}
    }
    __syncthreads();

    // partial table: prt[t*6+part] = sum over 32 of this block's 192 F values
    // of 1/(1 + e^{2 t/64} * F).  390 threads, 4 independent rcp chains.
    if (tid < 6 * TPTS) {
        int t    = tid / 6;
        int part = tid - 6 * t;
        float E = __expf((float)t * (2.0f / 64.0f));
        float a0 = 0.f, a1 = 0.f, a2 = 0.f, a3 = 0.f;
        #pragma unroll
        for (int k = 0; k < 32; k += 4) {
            a0 += frcp(fmaf(E, sp[SP_F + part + 6 * k],      1.0f));
            a1 += frcp(fmaf(E, sp[SP_F + part + 6 * k + 6],  1.0f));
            a2 += frcp(fmaf(E, sp[SP_F + part + 6 * k + 12], 1.0f));
            a3 += frcp(fmaf(E, sp[SP_F + part + 6 * k + 18], 1.0f));
        }
        sp[SP_PRT + tid] = (a0 + a1) + (a2 + a3);
    }
    __syncthreads();

    // write this block's 65-entry partial row (plain store, replay-safe)
    if (tid < TPTS) {
        const float* q = sp + SP_PRT + 6 * tid;
        d_part[n][rem][tid] = ((q[0] + q[1]) + (q[2] + q[3])) + (q[4] + q[5]);
    }

    imgbar(n);                                 // single per-image barrier

    // ---------------- Phase 3: reduce table; out = M - W(diff) -------------
    // parallel reduce: 260 threads, each sums 9 of the 36 slices for one t
    if (tid < 4 * TPTS) {
        int t = tid % TPTS;
        int g = tid / TPTS;                    // 0..3
        const float* p = &d_part[n][g * 9][t];
        float a0 = 0.f, a1 = 0.f, a2 = 0.f;
        #pragma unroll
        for (int s = 0; s < 9; s += 3) {
            a0 += p[(s + 0) * TPTS];
            a1 += p[(s + 1) * TPTS];
            a2 += p[(s + 2) * TPTS];
        }
        sp[SP_RD + tid] = (a0 + a1) + a2;
    }
    float tw[KS];
    #pragma unroll
    for (int k = 0; k < KS; k++) tw[k] = sp[SP_KW + k];
    __syncthreads();

    if (tid < TPTS) {
        float s = (sp[SP_RD + tid] + sp[SP_RD + TPTS + tid])
                + (sp[SP_RD + 2 * TPTS + tid] + sp[SP_RD + 3 * TPTS + tid]);
        sp[SP_TBL + tid] = 1.0f - s * (2.0f / (float)NPIX);
    }
    __syncthreads();

    // diff tile from persisted IN tile (zero outside the image)
    for (int i = tid; i < TROWS * TCOLS; i += TB) {
        int r  = i / TCOLS;
        int xc = i % TCOLS - KR;
        int yy = y0 - KR + r;
        float d = 0.0f;
        if ((unsigned)yy < HW && (unsigned)xc < HW) {
            float u = sp[SP_IN + i] * 64.0f;
            u = fminf(fmaxf(u, 0.0f), 63.999f);
            int   i0 = (int)u;
            float fr = u - (float)i0;
            float t0 = sp[SP_TBL + i0], t1 = sp[SP_TBL + i0 + 1];
            d = fmaf(t1 - t0, fr, t0);
        }
        sp[SP_DF + i] = d;
    }
    __syncthreads();

    // horizontal pass (W conv, 3 independent chains)
    for (int i = tid; i < TROWS * HW; i += TB) {
        int r = i / HW, x = i % HW;
        const float* row = sp + SP_DF + r * TCOLS + x;
        float a0 = 0.f, a1 = 0.f, a2 = 0.f;
        #pragma unroll
        for (int k = 0; k < 7; k++) {
            a0 = fmaf(row[k],      tw[k],      a0);
            a1 = fmaf(row[k + 7],  tw[k + 7],  a1);
            a2 = fmaf(row[k + 14], tw[k + 14], a2);
        }
        sp[SP_H3 + i] = (a0 + a1) + a2;
    }
    __syncthreads();

    // vertical pass (192 threads, 3 chains) + final subtraction (L = 1)
    if (tid < YT * HW) {
        int yo = tid / HW, x = tid % HW;
        float a0 = 0.f, a1 = 0.f, a2 = 0.f;
        #pragma unroll
        for (int k = 0; k < 7; k++) {
            a0 = fmaf(sp[SP_H3 + (yo + k) * HW + x],      tw[k],      a0);
            a1 = fmaf(sp[SP_H3 + (yo + k + 7) * HW + x],  tw[k + 7],  a1);
            a2 = fmaf(sp[SP_H3 + (yo + k + 14) * HW + x], tw[k + 14], a2);
        }
        float sw = (a0 + a1) + a2;
        out[((n * HW + y0 + yo) * HW + x) * CH + c] = sp[SP_M + tid] - sw;
    }
}

extern "C" void kernel_launch(void* const* d_in, const int* in_sizes, int n_in,
                              void* d_out, int out_size) {
    const float* in = (const float*)d_in[0];
    const float* gm = (const float*)d_in[1];
    const float* gw = (const float*)d_in[2];
    const float* gg = (const float*)d_in[3];
    float* out = (float*)d_out;

    inrf_fused<<<GRID, TB>>>(in, gm, gw, gg, out);
}

// round 12
// speedup vs baseline: 1.1658x; 1.0226x over previous
#include <cuda_runtime.h>
#include <math.h>

// Problem constants
#define NIMG   4
#define HW     48
#define CH     3
#define NPIX   6912              // per image
#define KS     21
#define KR     10

// Config
#define TPTS   65                // x-grid: t/64, t=0..64
#define GRID   144               // 1 block/SM -> all co-resident, safe spin barrier
#define TB     512
#define YT     4                 // output rows per conv tile (144 = 4n*3c*12)
#define TROWS  (YT + KS - 1)     // 24
#define TCOLS  (HW + KS - 1)     // 68
#define BPI    36                // blocks per image

// Scratch (device globals; no allocation). d_part overwritten each run.
// Transposed layout: [n][t][slice] -> reduce reads 36 contiguous floats.
__device__ __align__(16) float d_part[NIMG][TPTS][BPI];
__device__ unsigned g_cntb[NIMG];
__device__ unsigned g_genb[NIMG];

// Shared pool (floats):
//  persist: IN @0 (1632), KG@1632 KM@1656 KW@1680, M @1704 (192),
//           S @1896 (96), P @1992 (96)
//  P1: H1 @2088 (1152), H2 @3240 (1152)
//  P2: PRT @2088 (390, reuses H1)
//  P3: TBL @2088 (66), DF @2160 (1632), H3 @3852 (1152)
#define SP_IN   0
#define SP_KG   1632
#define SP_KM   1656
#define SP_KW   1680
#define SP_M    1704
#define SP_S    1896
#define SP_P    1992
#define SP_H1   2088
#define SP_H2   3240
#define SP_PRT  2088
#define SP_TBL  2088
#define SP_DF   2160
#define SP_H3   3852
#define POOL    5056             // 20224 B static smem

__device__ __forceinline__ float frcp(float x) {
    float r; asm("rcp.approx.f32 %0, %1;" : "=f"(r) : "f"(x)); return r;
}

// f32x2 packed helpers (FFMA2 via PTX fma.rn.f32x2)
__device__ __forceinline__ unsigned long long pack2(float lo, float hi) {
    unsigned long long d;
    asm("mov.b64 %0, {%1, %2};" : "=l"(d) : "r"(__float_as_uint(lo)), "r"(__float_as_uint(hi)));
    return d;
}
__device__ __forceinline__ void unpack2(unsigned long long v, float& lo, float& hi) {
    unsigned a, b;
    asm("mov.b64 {%0, %1}, %2;" : "=r"(a), "=r"(b) : "l"(v));
    lo = __uint_as_float(a); hi = __uint_as_float(b);
}
__device__ __forceinline__ void fma2(unsigned long long& acc,
                                     unsigned long long a, unsigned long long b) {
    asm("fma.rn.f32x2 %0, %1, %2, %0;" : "+l"(acc) : "l"(a), "l"(b));
}

// Per-image spin barrier, CG-style: fences only in the leader thread.
__device__ __forceinline__ void imgbar(int idx) {
    __syncthreads();
    if (threadIdx.x == 0) {
        volatile unsigned* vgen = (volatile unsigned*)&g_genb[idx];
        __threadfence();                      // order d_part stores before arrive
        unsigned gen = *vgen;
        if (atomicAdd(&g_cntb[idx], 1u) == BPI - 1) {
            g_cntb[idx] = 0;
            __threadfence();
            *vgen = gen + 1;
        } else {
            while (*vgen == gen) {}
        }
        __threadfence();                      // acquire before block reads d_part
    }
    __syncthreads();
}

// One warp builds a unit-L2 1D Gaussian (2D kernel = exact outer product).
__device__ __forceinline__ void make_k1d(float gamma, float* out) {
    int lane = threadIdx.x & 31;
    float inv2s2 = 0.5f * gamma * gamma;
    const float step = (21.0f / 32.0f) / 20.0f;
    const float mean = 21.0f / 64.0f;
    float v = 0.0f;
    if (lane < KS) {
        float d = (float)lane * step - mean;
        v = expf(-d * d * inv2s2);
    }
    float ss = v * v;
    #pragma unroll
    for (int o = 16; o > 0; o >>= 1) ss += __shfl_xor_sync(0xffffffffu, ss, o);
    if (lane < KS) out[lane] = v * rsqrtf(ss);
}

__global__ __launch_bounds__(TB, 1)
void inrf_fused(const float* __restrict__ in,
                const float* __restrict__ gm,
                const float* __restrict__ gw,
                const float* __restrict__ gg,
                float* __restrict__ out) {
    __shared__ float sp[POOL];

    const int tid  = threadIdx.x;
    const int warp = tid >> 5;

    // Decomposition: 144 = 4n * 36; within image: 3c * 12 ytiles
    const int b   = blockIdx.x;
    const int n   = b / BPI;
    const int rem = b % BPI;
    const int c   = rem / 12;
    const int y0  = (rem % 12) * YT;

    // ---------------- Phase 1: convs + per-block partial tanh-table --------
    if      (warp == 0) make_k1d(gg[c], sp + SP_KG);
    else if (warp == 1) make_k1d(gm[c], sp + SP_KM);
    else if (warp == 2) make_k1d(gw[c], sp + SP_KW);

    // zero-padded input tile (rows y0-10..y0+13, cols -10..57), channel c
    for (int i = tid; i < TROWS * TCOLS; i += TB) {
        int r  = i / TCOLS;
        int xc = i % TCOLS - KR;
        int yy = y0 - KR + r;
        float v = 0.0f;
        if ((unsigned)yy < HW && (unsigned)xc < HW)
            v = in[((n * HW + yy) * HW + xc) * CH + c];
        sp[SP_IN + i] = v;
    }
    __syncthreads();

    // packed taps (lo=G, hi=M) -> registers
    unsigned long long tk[KS];
    #pragma unroll
    for (int k = 0; k < KS; k++) tk[k] = pack2(sp[SP_KG + k], sp[SP_KM + k]);

    // horizontal pass, both convs (packed FMA, 3 independent chains)
    for (int i = tid; i < TROWS * HW; i += TB) {
        int r = i / HW, x = i % HW;
        const float* row = sp + SP_IN + r * TCOLS + x;
        unsigned long long a0 = 0ull, a1 = 0ull, a2 = 0ull;
        #pragma unroll
        for (int k = 0; k < 7; k++) {
            float v0 = row[k], v1 = row[k + 7], v2 = row[k + 14];
            fma2(a0, pack2(v0, v0), tk[k]);
            fma2(a1, pack2(v1, v1), tk[k + 7]);
            fma2(a2, pack2(v2, v2), tk[k + 14]);
        }
        float s1a, s2a, s1b, s2b, s1c, s2c;
        unpack2(a0, s1a, s2a); unpack2(a1, s1b, s2b); unpack2(a2, s1c, s2c);
        sp[SP_H1 + i] = (s1a + s1b) + s1c;     // G partial
        sp[SP_H2 + i] = (s2a + s2b) + s2c;     // M partial
    }
    __syncthreads();

    // vertical pass (192 threads, 3 chains): M -> smem; F = e^{-2 blur};
    // pair-fold F via shfl: S = F0+F1, P = F0*F1 per adjacent pixel pair.
    if (tid < YT * HW) {
        int yo = tid / HW, x = tid % HW;
        unsigned long long a0 = 0ull, a1 = 0ull, a2 = 0ull;
        #pragma unroll
        for (int k = 0; k < 7; k++) {
            int o0 = (yo + k) * HW + x;
            int o1 = (yo + k + 7) * HW + x;
            int o2 = (yo + k + 14) * HW + x;
            fma2(a0, pack2(sp[SP_H1 + o0], sp[SP_H2 + o0]), tk[k]);
            fma2(a1, pack2(sp[SP_H1 + o1], sp[SP_H2 + o1]), tk[k + 7]);
            fma2(a2, pack2(sp[SP_H1 + o2], sp[SP_H2 + o2]), tk[k + 14]);
        }
        float g0, m0, g1, m1, g2, m2;
        unpack2(a0, g0, m0); unpack2(a1, g1, m1); unpack2(a2, g2, m2);
        sp[SP_M + tid] = (m0 + m1) + m2;
        float F  = __expf(-2.0f * ((g0 + g1) + g2));
        float Fo = __shfl_xor_sync(0xffffffffu, F, 1);
        if ((tid & 1) == 0) {
            sp[SP_S + (tid >> 1)] = F + Fo;
            sp[SP_P + (tid >> 1)] = F * Fo;
        }
    }
    __syncthreads();

    // partial table (pairwise): prt[t*6+part] = sum over 16 pairs of
    //   (2 + E*S) / (1 + E*S + E^2*P)   == 1/(1+E F0) + 1/(1+E F1)
    // 390 threads, 4 independent rcp chains, 1 MUFU per 2 pixels.
    if (tid < 6 * TPTS) {
        int t    = tid / 6;
        int part = tid - 6 * t;
        float E  = __expf((float)t * (2.0f / 64.0f));
        float E2 = E * E;
        float a0 = 0.f, a1 = 0.f, a2 = 0.f, a3 = 0.f;
        #pragma unroll
        for (int k = 0; k < 16; k += 4) {
            float s0 = sp[SP_S + part + 6 * (k + 0)], p0 = sp[SP_P + part + 6 * (k + 0)];
            float s1 = sp[SP_S + part + 6 * (k + 1)], p1 = sp[SP_P + part + 6 * (k + 1)];
            float s2 = sp[SP_S + part + 6 * (k + 2)], p2 = sp[SP_P + part + 6 * (k + 2)];
            float s3 = sp[SP_S + part + 6 * (k + 3)], p3 = sp[SP_P + part + 6 * (k + 3)];
            a0 += fmaf(E, s0, 2.0f) * frcp(fmaf(E2, p0, fmaf(E, s0, 1.0f)));
            a1 += fmaf(E, s1, 2.0f) * frcp(fmaf(E2, p1, fmaf(E, s1, 1.0f)));
            a2 += fmaf(E, s2, 2.0f) * frcp(fmaf(E2, p2, fmaf(E, s2, 1.0f)));
            a3 += fmaf(E, s3, 2.0f) * frcp(fmaf(E2, p3, fmaf(E, s3, 1.0f)));
        }
        sp[SP_PRT + tid] = (a0 + a1) + (a2 + a3);
    }
    __syncthreads();

    // write this block's 65-entry partial column (transposed, replay-safe)
    if (tid < TPTS) {
        const float* q = sp + SP_PRT + 6 * tid;
        d_part[n][tid][rem] = ((q[0] + q[1]) + (q[2] + q[3])) + (q[4] + q[5]);
    }

    imgbar(n);                                 // single per-image barrier

    // ---------------- Phase 3: reduce table; out = M - W(diff) -------------
    // merged reduce+table: 65 threads, 9 contiguous float4 loads each (MLP 9)
    if (tid < TPTS) {
        const float4* p4 = (const float4*)&d_part[n][tid][0];
        float a0 = 0.f, a1 = 0.f, a2 = 0.f, a3 = 0.f;
        #pragma unroll
        for (int s = 0; s < 9; s += 3) {
            float4 v0 = p4[s], v1 = p4[s + 1], v2 = p4[s + 2];
            a0 += v0.x + v0.y;  a1 += v0.z + v0.w;
            a2 += v1.x + v1.y;  a3 += v1.z + v1.w;
            a0 += v2.x + v2.y;  a1 += v2.z + v2.w;
        }
        float s = (a0 + a1) + (a2 + a3);
        sp[SP_TBL + tid] = 1.0f - s * (2.0f / (float)NPIX);
    }
    float tw[KS];
    #pragma unroll
    for (int k = 0; k < KS; k++) tw[k] = sp[SP_KW + k];
    __syncthreads();

    // diff tile from persisted IN tile (zero outside the image)
    for (int i = tid; i < TROWS * TCOLS; i += TB) {
        int r  = i / TCOLS;
        int xc = i % TCOLS - KR;
        int yy = y0 - KR + r;
        float d = 0.0f;
        if ((unsigned)yy < HW && (unsigned)xc < HW) {
            float u = sp[SP_IN + i] * 64.0f;
            u = fminf(fmaxf(u, 0.0f), 63.999f);
            int   i0 = (int)u;
            float fr = u - (float)i0;
            float t0 = sp[SP_TBL + i0], t1 = sp[SP_TBL + i0 + 1];
            d = fmaf(t1 - t0, fr, t0);
        }
        sp[SP_DF + i] = d;
    }
    __syncthreads();

    // horizontal pass (W conv, 3 independent chains)
    for (int i = tid; i < TROWS * HW; i += TB) {
        int r = i / HW, x = i % HW;
        const float* row = sp + SP_DF + r * TCOLS + x;
        float a0 = 0.f, a1 = 0.f, a2 = 0.f;
        #pragma unroll
        for (int k = 0; k < 7; k++) {
            a0 = fmaf(row[k],      tw[k],      a0);
            a1 = fmaf(row[k + 7],  tw[k + 7],  a1);
            a2 = fmaf(row[k + 14], tw[k + 14], a2);
        }
        sp[SP_H3 + i] = (a0 + a1) + a2;
    }
    __syncthreads();

    // vertical pass (192 threads, 3 chains) + final subtraction (L = 1)
    if (tid < YT * HW) {
        int yo = tid / HW, x = tid % HW;
        float a0 = 0.f, a1 = 0.f, a2 = 0.f;
        #pragma unroll
        for (int k = 0; k < 7; k++) {
            a0 = fmaf(sp[SP_H3 + (yo + k) * HW + x],      tw[k],      a0);
            a1 = fmaf(sp[SP_H3 + (yo + k + 7) * HW + x],  tw[k + 7],  a1);
            a2 = fmaf(sp[SP_H3 + (yo + k + 14) * HW + x], tw[k + 14], a2);
        }
        float sw = (a0 + a1) + a2;
        out[((n * HW + y0 + yo) * HW + x) * CH + c] = sp[SP_M + tid] - sw;
    }
}

extern "C" void kernel_launch(void* const* d_in, const int* in_sizes, int n_in,
                              void* d_out, int out_size) {
    const float* in = (const float*)d_in[0];
    const float* gm = (const float*)d_in[1];
    const float* gw = (const float*)d_in[2];
    const float* gg = (const float*)d_in[3];
    float* out = (float*)d_out;

    inrf_fused<<<GRID, TB>>>(in, gm, gw, gg, out);
}